// round 16
// baseline (speedup 1.0000x reference)
#include <cuda_runtime.h>
#include <cstdint>

#define NN 50000
#define NE 600000
#define HID 128
#define SCAN_B 1024
#define NBLK ((NN + SCAN_B - 1) / SCAN_B)   // 49 scan blocks
#define GM 128      // GEMM block m-tile
#define GK 32       // GEMM k-chunk
#define PAD 36      // smem row stride in words (bank map 4g+t, conflict-free)

// Scratch (static device globals — no runtime allocation).
__device__ __align__(256) float g_q[(size_t)NN * HID];
__device__ __align__(256) float g_k[(size_t)NN * HID];
__device__ __align__(256) float g_v[(size_t)NN * HID];
__device__ __align__(256) int   g_src[NE];
__device__ __align__(256) int   g_dst[NE];
__device__ __align__(256) int   g_count[NN];
__device__ __align__(256) int   g_start[NN + 1];
__device__ __align__(256) int   g_cursor[NN];
__device__ __align__(256) int2  g_es[NE];        // (edge id, src) sorted by dst
__device__ __align__(256) int   g_bsum[NBLK];
__device__ __align__(256) int   g_boff[NBLK];
__device__ int g_is_i32;

// ---------------------------------------------------------------------------
// TF32 helpers (mma.sync m16n8k8 — tensor pipe).
// ---------------------------------------------------------------------------
__device__ __forceinline__ uint32_t f2tf32(float f) {
    uint32_t r; asm("cvt.rna.tf32.f32 %0, %1;" : "=r"(r) : "f"(f)); return r;
}
__device__ __forceinline__ void mma_tf32(float* c, const uint32_t* a,
                                         uint32_t b0, uint32_t b1) {
    asm volatile(
        "mma.sync.aligned.m16n8k8.row.col.f32.tf32.tf32.f32 "
        "{%0,%1,%2,%3}, {%4,%5,%6,%7}, {%8,%9}, {%0,%1,%2,%3};"
        : "+f"(c[0]), "+f"(c[1]), "+f"(c[2]), "+f"(c[3])
        : "r"(a[0]), "r"(a[1]), "r"(a[2]), "r"(a[3]), "r"(b0), "r"(b1));
}
// Convert a float4 to 4 tf32 words.
__device__ __forceinline__ uint4 f4_to_tf32(float4 v) {
    uint4 r;
    r.x = f2tf32(v.x); r.y = f2tf32(v.y);
    r.z = f2tf32(v.z); r.w = f2tf32(v.w);
    return r;
}

// ---------------------------------------------------------------------------
// Kernel Z: zero counters + dtype flag + detection in one pass.
// ---------------------------------------------------------------------------
__global__ void zero_and_detect(const unsigned int* __restrict__ ei_words) {
    int t = blockIdx.x * blockDim.x + threadIdx.x;
    if (t == 0) g_is_i32 = 0;
    for (int i = t; i < NN; i += blockDim.x * gridDim.x) g_count[i] = 0;
    unsigned int acc = 0;
    for (int i = t; i < NE; i += blockDim.x * gridDim.x)
        acc |= ei_words[2 * i + 1];
    if (acc) atomicOr(&g_is_i32, 1);
}

// ---------------------------------------------------------------------------
// Kernel B: decode edge_index into g_src/g_dst AND histogram dst degrees.
// ---------------------------------------------------------------------------
__global__ void convert_idx(const unsigned int* __restrict__ ei_words) {
    int t = blockIdx.x * blockDim.x + threadIdx.x;
    int i32 = g_is_i32;
    for (int e = t; e < NE; e += blockDim.x * gridDim.x) {
        int s, d;
        if (i32) {
            s = (int)ei_words[e];
            d = (int)ei_words[NE + e];
        } else {
            s = (int)ei_words[2 * (size_t)e];
            d = (int)ei_words[2 * ((size_t)NE + e)];
        }
        g_src[e] = s;
        g_dst[e] = d;
        atomicAdd(&g_count[d], 1);
    }
}

// ---------------------------------------------------------------------------
// 3-phase parallel scan.
// ---------------------------------------------------------------------------
__global__ __launch_bounds__(SCAN_B) void scan_phase1() {
    __shared__ int ps[SCAN_B];
    int tid = threadIdx.x;
    int idx = blockIdx.x * SCAN_B + tid;
    int val = (idx < NN) ? g_count[idx] : 0;
    ps[tid] = val;
    __syncthreads();
#pragma unroll
    for (int d = 1; d < SCAN_B; d <<= 1) {
        int v = (tid >= d) ? ps[tid - d] : 0;
        __syncthreads();
        ps[tid] += v;
        __syncthreads();
    }
    if (idx < NN) g_start[idx] = ps[tid] - val;
    if (tid == SCAN_B - 1) g_bsum[blockIdx.x] = ps[tid];
}

__global__ void scan_phase2() {
    int l = threadIdx.x;             // 64 threads, NBLK=49 <= 64
    int v = (l < NBLK) ? g_bsum[l] : 0;
    int orig = v;
    __shared__ int s[64];
    s[l] = v;
    __syncthreads();
#pragma unroll
    for (int d = 1; d < 64; d <<= 1) {
        int t = (l >= d) ? s[l - d] : 0;
        __syncthreads();
        s[l] += t;
        __syncthreads();
    }
    if (l < NBLK) g_boff[l] = s[l] - orig;
    if (l == 63) g_start[NN] = s[63];
}

__global__ __launch_bounds__(SCAN_B) void scan_phase3() {
    int idx = blockIdx.x * SCAN_B + threadIdx.x;
    if (idx < NN) {
        int v = g_start[idx] + g_boff[blockIdx.x];
        g_start[idx] = v;
        g_cursor[idx] = v;
    }
}

// ---------------------------------------------------------------------------
// Kernel D: permute (edge id, src) pairs into dst-sorted order.
// ---------------------------------------------------------------------------
__global__ void permute_idx() {
    int t = blockIdx.x * blockDim.x + threadIdx.x;
    for (int e = t; e < NE; e += blockDim.x * gridDim.x) {
        int d = g_dst[e];
        int pos = atomicAdd(&g_cursor[d], 1);
        g_es[pos] = make_int2(e, g_src[e]);
    }
}

// ---------------------------------------------------------------------------
// Kernel 1: QKV GEMM on tensor cores (TF32 mma.sync m16n8k8).
// TF32 conversion happens ONCE at smem-fill time (smem holds tf32 bit
// patterns); fragment loads are raw LDS -> 3x fewer cvt instructions than
// converting at use time. Block tile 128x128, K chunks of 32, warp grid
// 4m x 2n, per-warp 32x64. B-frag = W[o][d] read directly (no transpose).
// ---------------------------------------------------------------------------
__global__ __launch_bounds__(256, 2) void qkv_gemm_tc(
    const float* __restrict__ x,
    const float* __restrict__ Wq,
    const float* __restrict__ Wk,
    const float* __restrict__ Wv) {

    __shared__ uint32_t As[GM * PAD];
    __shared__ uint32_t Ws[HID * PAD];

    int m = blockIdx.y;
    const float* W = (m == 0) ? Wq : (m == 1) ? Wk : Wv;
    float* out = (m == 0) ? g_q : (m == 1) ? g_k : g_v;

    int node0 = blockIdx.x * GM;
    int tid = threadIdx.x;
    int warp = tid >> 5;
    int lane = tid & 31;
    int g = lane >> 2;       // group 0..7
    int t = lane & 3;        // thread-in-group 0..3
    int wm = warp >> 1;      // 0..3
    int wn = warp & 1;       // 0..1

    float c[2][8][4];
#pragma unroll
    for (int mt = 0; mt < 2; mt++)
#pragma unroll
        for (int nt = 0; nt < 8; nt++)
#pragma unroll
            for (int i = 0; i < 4; i++) c[mt][nt][i] = 0.f;

    const float4* x4 = (const float4*)x;
    const float4* W4 = (const float4*)W;

#pragma unroll
    for (int kc = 0; kc < HID / GK; kc++) {
        int k0 = kc * GK;
        if (kc) __syncthreads();
        // A chunk: 128 rows x 32 floats; cvt to tf32 at fill.
#pragma unroll
        for (int i = 0; i < 4; i++) {
            int idx = tid + i * 256;
            int r = idx >> 3;          // 8 float4 per row
            int c4 = idx & 7;
            int gn = node0 + r;
            float4 val = (gn < NN) ? x4[(size_t)gn * 32 + (k0 >> 2) + c4]
                                   : make_float4(0.f, 0.f, 0.f, 0.f);
            *(uint4*)&As[r * PAD + c4 * 4] = f4_to_tf32(val);
        }
        // W chunk: 128 rows x 32 floats; cvt to tf32 at fill.
#pragma unroll
        for (int i = 0; i < 4; i++) {
            int idx = tid + i * 256;
            int r = idx >> 3;
            int c4 = idx & 7;
            *(uint4*)&Ws[r * PAD + c4 * 4] =
                f4_to_tf32(W4[(size_t)r * 32 + (k0 >> 2) + c4]);
        }
        __syncthreads();

#pragma unroll
        for (int ks = 0; ks < GK / 8; ks++) {
            int kk = ks * 8;
            uint32_t a[2][4];
#pragma unroll
            for (int mt = 0; mt < 2; mt++) {
                int mrow = wm * 32 + mt * 16;
                a[mt][0] = As[(mrow + g) * PAD + kk + t];
                a[mt][1] = As[(mrow + g + 8) * PAD + kk + t];
                a[mt][2] = As[(mrow + g) * PAD + kk + t + 4];
                a[mt][3] = As[(mrow + g + 8) * PAD + kk + t + 4];
            }
#pragma unroll
            for (int nt = 0; nt < 8; nt++) {
                int o = wn * 64 + nt * 8 + g;
                uint32_t b0 = Ws[o * PAD + kk + t];
                uint32_t b1 = Ws[o * PAD + kk + t + 4];
                mma_tf32(c[0][nt], a[0], b0, b1);
                mma_tf32(c[1][nt], a[1], b0, b1);
            }
        }
    }

    // Store: c0,c1 -> row (base+g), cols 2t,2t+1; c2,c3 -> row (base+g+8).
#pragma unroll
    for (int mt = 0; mt < 2; mt++) {
        int r0 = node0 + wm * 32 + mt * 16 + g;
        int r1 = r0 + 8;
#pragma unroll
        for (int nt = 0; nt < 8; nt++) {
            int col = wn * 64 + nt * 8 + 2 * t;
            if (r0 < NN)
                *(float2*)&out[(size_t)r0 * HID + col] =
                    make_float2(c[mt][nt][0], c[mt][nt][1]);
            if (r1 < NN)
                *(float2*)&out[(size_t)r1 * HID + col] =
                    make_float2(c[mt][nt][2], c[mt][nt][3]);
        }
    }
}

// ---------------------------------------------------------------------------
// Kernel 2: FUSED dst-sorted edge kernel (R13 best: one warp = one CTA =
// one node, unroll 4 -> 12 LDG.128 in flight). q loaded once per node; per
// edge k,v gathers (L2-resident) + coalesced w_ij row (__ldcs) + cutoff.
// ---------------------------------------------------------------------------
__global__ __launch_bounds__(32) void edge_fused(
    const float* __restrict__ w_ij,
    const float* __restrict__ cutoff,
    float* __restrict__ out) {

    int node = blockIdx.x;
    int l = threadIdx.x;

    int p     = g_start[node];
    int e_end = g_start[node + 1];

    float4 q = *(const float4*)&g_q[(size_t)node * HID + 4 * l];
    float4 acc = make_float4(0.f, 0.f, 0.f, 0.f);

    for (; p + 4 <= e_end; p += 4) {
        int2 es0 = g_es[p];
        int2 es1 = g_es[p + 1];
        int2 es2 = g_es[p + 2];
        int2 es3 = g_es[p + 3];

        float4 k0 = *(const float4*)&g_k[(size_t)es0.y * HID + 4 * l];
        float4 k1 = *(const float4*)&g_k[(size_t)es1.y * HID + 4 * l];
        float4 k2 = *(const float4*)&g_k[(size_t)es2.y * HID + 4 * l];
        float4 k3 = *(const float4*)&g_k[(size_t)es3.y * HID + 4 * l];
        float4 v0 = *(const float4*)&g_v[(size_t)es0.y * HID + 4 * l];
        float4 v1 = *(const float4*)&g_v[(size_t)es1.y * HID + 4 * l];
        float4 v2 = *(const float4*)&g_v[(size_t)es2.y * HID + 4 * l];
        float4 v3 = *(const float4*)&g_v[(size_t)es3.y * HID + 4 * l];
        float4 w0 = __ldcs((const float4*)&w_ij[(size_t)es0.x * HID + 4 * l]);
        float4 w1 = __ldcs((const float4*)&w_ij[(size_t)es1.x * HID + 4 * l]);
        float4 w2 = __ldcs((const float4*)&w_ij[(size_t)es2.x * HID + 4 * l]);
        float4 w3 = __ldcs((const float4*)&w_ij[(size_t)es3.x * HID + 4 * l]);
        float  c0 = __ldg(&cutoff[es0.x]);
        float  c1 = __ldg(&cutoff[es1.x]);
        float  c2 = __ldg(&cutoff[es2.x]);
        float  c3 = __ldg(&cutoff[es3.x]);

        float p0 = q.x * w0.x * k0.x + q.y * w0.y * k0.y + q.z * w0.z * k0.z + q.w * w0.w * k0.w;
        float p1 = q.x * w1.x * k1.x + q.y * w1.y * k1.y + q.z * w1.z * k1.z + q.w * w1.w * k1.w;
        float p2 = q.x * w2.x * k2.x + q.y * w2.y * k2.y + q.z * w2.z * k2.z + q.w * w2.w * k2.w;
        float p3 = q.x * w3.x * k3.x + q.y * w3.y * k3.y + q.z * w3.z * k3.z + q.w * w3.w * k3.w;

        p0 += __shfl_xor_sync(0xffffffffu, p0, 1);
        p0 += __shfl_xor_sync(0xffffffffu, p0, 2);
        p1 += __shfl_xor_sync(0xffffffffu, p1, 1);
        p1 += __shfl_xor_sync(0xffffffffu, p1, 2);
        p2 += __shfl_xor_sync(0xffffffffu, p2, 1);
        p2 += __shfl_xor_sync(0xffffffffu, p2, 2);
        p3 += __shfl_xor_sync(0xffffffffu, p3, 1);
        p3 += __shfl_xor_sync(0xffffffffu, p3, 2);

        float a0 = p0 * 0.25f * c0;
        float a1 = p1 * 0.25f * c1;
        float a2 = p2 * 0.25f * c2;
        float a3 = p3 * 0.25f * c3;

        acc.x = fmaf(a0, v0.x, fmaf(a1, v1.x, fmaf(a2, v2.x, fmaf(a3, v3.x, acc.x))));
        acc.y = fmaf(a0, v0.y, fmaf(a1, v1.y, fmaf(a2, v2.y, fmaf(a3, v3.y, acc.y))));
        acc.z = fmaf(a0, v0.z, fmaf(a1, v1.z, fmaf(a2, v2.z, fmaf(a3, v3.z, acc.z))));
        acc.w = fmaf(a0, v0.w, fmaf(a1, v1.w, fmaf(a2, v2.w, fmaf(a3, v3.w, acc.w))));
    }
    for (; p < e_end; p++) {
        int2 es0 = g_es[p];
        float4 k0 = *(const float4*)&g_k[(size_t)es0.y * HID + 4 * l];
        float4 v0 = *(const float4*)&g_v[(size_t)es0.y * HID + 4 * l];
        float4 w0 = __ldcs((const float4*)&w_ij[(size_t)es0.x * HID + 4 * l]);
        float p0 = q.x * w0.x * k0.x + q.y * w0.y * k0.y + q.z * w0.z * k0.z + q.w * w0.w * k0.w;
        p0 += __shfl_xor_sync(0xffffffffu, p0, 1);
        p0 += __shfl_xor_sync(0xffffffffu, p0, 2);
        float a0 = p0 * 0.25f * __ldg(&cutoff[es0.x]);
        acc.x = fmaf(a0, v0.x, acc.x);
        acc.y = fmaf(a0, v0.y, acc.y);
        acc.z = fmaf(a0, v0.z, acc.z);
        acc.w = fmaf(a0, v0.w, acc.w);
    }

    __stcs((float4*)&out[(size_t)node * HID + 4 * l], acc);
}

// ---------------------------------------------------------------------------
extern "C" void kernel_launch(void* const* d_in, const int* in_sizes, int n_in,
                              void* d_out, int out_size) {
    const float* x      = (const float*)d_in[0];
    const float* w_ij   = (const float*)d_in[1];
    const unsigned int* ei = (const unsigned int*)d_in[2];
    const float* cutoff = (const float*)d_in[3];
    const float* Wq     = (const float*)d_in[4];
    const float* Wk     = (const float*)d_in[5];
    const float* Wv     = (const float*)d_in[6];
    float* out = (float*)d_out;

    static cudaStream_t s2 = nullptr;
    static cudaEvent_t evFork = nullptr, evSort = nullptr;
    static bool use_streams = false;
    if (!s2 && !evFork) {
        bool ok = (cudaStreamCreateWithFlags(&s2, cudaStreamNonBlocking) == cudaSuccess)
               && (cudaEventCreateWithFlags(&evFork, cudaEventDisableTiming) == cudaSuccess)
               && (cudaEventCreateWithFlags(&evSort, cudaEventDisableTiming) == cudaSuccess);
        use_streams = ok;
    }

    dim3 ggrid((NN + GM - 1) / GM, 3);   // 391 x 3

    if (use_streams) {
        cudaEventRecord(evFork, 0);
        cudaStreamWaitEvent(s2, evFork, 0);

        // s2: sort chain (hidden under the GEMM on main)
        zero_and_detect<<<148, 256, 0, s2>>>(ei);
        convert_idx<<<148, 256, 0, s2>>>(ei);
        scan_phase1<<<NBLK, SCAN_B, 0, s2>>>();
        scan_phase2<<<1, 64, 0, s2>>>();
        scan_phase3<<<NBLK, SCAN_B, 0, s2>>>();
        permute_idx<<<148, 256, 0, s2>>>();
        cudaEventRecord(evSort, s2);

        // main: tensor-core QKV GEMM
        qkv_gemm_tc<<<ggrid, 256>>>(x, Wq, Wk, Wv);

        // join: fused edge needs sort + qkv
        cudaStreamWaitEvent(0, evSort, 0);
        edge_fused<<<NN, 32>>>(w_ij, cutoff, out);
    } else {
        zero_and_detect<<<148, 256>>>(ei);
        convert_idx<<<148, 256>>>(ei);
        scan_phase1<<<NBLK, SCAN_B>>>();
        scan_phase2<<<1, 64>>>();
        scan_phase3<<<NBLK, SCAN_B>>>();
        permute_idx<<<148, 256>>>();
        qkv_gemm_tc<<<ggrid, 256>>>(x, Wq, Wk, Wv);
        edge_fused<<<NN, 32>>>(w_ij, cutoff, out);
    }
}

// round 17
// speedup vs baseline: 1.1074x; 1.1074x over previous
#include <cuda_runtime.h>
#include <cuda_fp16.h>
#include <cstdint>

#define NN 50000
#define NE 600000
#define HID 128
#define SCAN_B 1024
#define NBLK ((NN + SCAN_B - 1) / SCAN_B)   // 49 scan blocks
#define GM 128      // GEMM block m-tile
#define GK 32       // GEMM k-chunk
#define PAD 36      // smem row stride in words (bank map 4g+t, conflict-free)

// Scratch (static device globals — no runtime allocation).
__device__ __align__(256) float  g_q[(size_t)NN * HID];
__device__ __align__(256) __half g_kh[(size_t)NN * HID];   // fp16 k
__device__ __align__(256) __half g_vh[(size_t)NN * HID];   // fp16 v
__device__ __align__(256) int   g_src[NE];
__device__ __align__(256) int   g_dst[NE];
__device__ __align__(256) int   g_count[NN];
__device__ __align__(256) int   g_start[NN + 1];
__device__ __align__(256) int   g_cursor[NN];
__device__ __align__(256) int2  g_es[NE];        // (edge id, src) sorted by dst
__device__ __align__(256) int   g_bsum[NBLK];
__device__ __align__(256) int   g_boff[NBLK];
__device__ int g_is_i32;

// ---------------------------------------------------------------------------
// TF32 helpers (mma.sync m16n8k8 — tensor pipe).
// ---------------------------------------------------------------------------
__device__ __forceinline__ uint32_t f2tf32(float f) {
    uint32_t r; asm("cvt.rna.tf32.f32 %0, %1;" : "=r"(r) : "f"(f)); return r;
}
__device__ __forceinline__ void mma_tf32(float* c, const uint32_t* a,
                                         uint32_t b0, uint32_t b1) {
    asm volatile(
        "mma.sync.aligned.m16n8k8.row.col.f32.tf32.tf32.f32 "
        "{%0,%1,%2,%3}, {%4,%5,%6,%7}, {%8,%9}, {%0,%1,%2,%3};"
        : "+f"(c[0]), "+f"(c[1]), "+f"(c[2]), "+f"(c[3])
        : "r"(a[0]), "r"(a[1]), "r"(a[2]), "r"(a[3]), "r"(b0), "r"(b1));
}
__device__ __forceinline__ uint4 f4_to_tf32(float4 v) {
    uint4 r;
    r.x = f2tf32(v.x); r.y = f2tf32(v.y);
    r.z = f2tf32(v.z); r.w = f2tf32(v.w);
    return r;
}
// Load 4 consecutive halves (8B) and widen to float4.
__device__ __forceinline__ float4 ld_half4(const __half* p) {
    uint2 raw = *(const uint2*)p;
    float2 lo = __half22float2(*(__half2*)&raw.x);
    float2 hi = __half22float2(*(__half2*)&raw.y);
    return make_float4(lo.x, lo.y, hi.x, hi.y);
}

// ---------------------------------------------------------------------------
// Kernel Z: zero counters + dtype flag + detection in one pass.
// ---------------------------------------------------------------------------
__global__ void zero_and_detect(const unsigned int* __restrict__ ei_words) {
    int t = blockIdx.x * blockDim.x + threadIdx.x;
    if (t == 0) g_is_i32 = 0;
    for (int i = t; i < NN; i += blockDim.x * gridDim.x) g_count[i] = 0;
    unsigned int acc = 0;
    for (int i = t; i < NE; i += blockDim.x * gridDim.x)
        acc |= ei_words[2 * i + 1];
    if (acc) atomicOr(&g_is_i32, 1);
}

// ---------------------------------------------------------------------------
// Kernel B: decode edge_index into g_src/g_dst AND histogram dst degrees.
// ---------------------------------------------------------------------------
__global__ void convert_idx(const unsigned int* __restrict__ ei_words) {
    int t = blockIdx.x * blockDim.x + threadIdx.x;
    int i32 = g_is_i32;
    for (int e = t; e < NE; e += blockDim.x * gridDim.x) {
        int s, d;
        if (i32) {
            s = (int)ei_words[e];
            d = (int)ei_words[NE + e];
        } else {
            s = (int)ei_words[2 * (size_t)e];
            d = (int)ei_words[2 * ((size_t)NE + e)];
        }
        g_src[e] = s;
        g_dst[e] = d;
        atomicAdd(&g_count[d], 1);
    }
}

// ---------------------------------------------------------------------------
// 3-phase parallel scan.
// ---------------------------------------------------------------------------
__global__ __launch_bounds__(SCAN_B) void scan_phase1() {
    __shared__ int ps[SCAN_B];
    int tid = threadIdx.x;
    int idx = blockIdx.x * SCAN_B + tid;
    int val = (idx < NN) ? g_count[idx] : 0;
    ps[tid] = val;
    __syncthreads();
#pragma unroll
    for (int d = 1; d < SCAN_B; d <<= 1) {
        int v = (tid >= d) ? ps[tid - d] : 0;
        __syncthreads();
        ps[tid] += v;
        __syncthreads();
    }
    if (idx < NN) g_start[idx] = ps[tid] - val;
    if (tid == SCAN_B - 1) g_bsum[blockIdx.x] = ps[tid];
}

__global__ void scan_phase2() {
    int l = threadIdx.x;             // 64 threads, NBLK=49 <= 64
    int v = (l < NBLK) ? g_bsum[l] : 0;
    int orig = v;
    __shared__ int s[64];
    s[l] = v;
    __syncthreads();
#pragma unroll
    for (int d = 1; d < 64; d <<= 1) {
        int t = (l >= d) ? s[l - d] : 0;
        __syncthreads();
        s[l] += t;
        __syncthreads();
    }
    if (l < NBLK) g_boff[l] = s[l] - orig;
    if (l == 63) g_start[NN] = s[63];
}

__global__ __launch_bounds__(SCAN_B) void scan_phase3() {
    int idx = blockIdx.x * SCAN_B + threadIdx.x;
    if (idx < NN) {
        int v = g_start[idx] + g_boff[blockIdx.x];
        g_start[idx] = v;
        g_cursor[idx] = v;
    }
}

// ---------------------------------------------------------------------------
// Kernel D: permute (edge id, src) pairs into dst-sorted order.
// ---------------------------------------------------------------------------
__global__ void permute_idx() {
    int t = blockIdx.x * blockDim.x + threadIdx.x;
    for (int e = t; e < NE; e += blockDim.x * gridDim.x) {
        int d = g_dst[e];
        int pos = atomicAdd(&g_cursor[d], 1);
        g_es[pos] = make_int2(e, g_src[e]);
    }
}

// ---------------------------------------------------------------------------
// Kernel 1: QKV GEMM on tensor cores (TF32 mma.sync m16n8k8).
// q (m=0) stored fp32; k (m=1) and v (m=2) stored fp16 (half2 per col-pair)
// to halve the edge kernel's gather traffic.
// ---------------------------------------------------------------------------
__global__ __launch_bounds__(256, 2) void qkv_gemm_tc(
    const float* __restrict__ x,
    const float* __restrict__ Wq,
    const float* __restrict__ Wk,
    const float* __restrict__ Wv) {

    __shared__ uint32_t As[GM * PAD];
    __shared__ uint32_t Ws[HID * PAD];

    int m = blockIdx.y;
    const float* W = (m == 0) ? Wq : (m == 1) ? Wk : Wv;

    int node0 = blockIdx.x * GM;
    int tid = threadIdx.x;
    int warp = tid >> 5;
    int lane = tid & 31;
    int g = lane >> 2;       // group 0..7
    int t = lane & 3;        // thread-in-group 0..3
    int wm = warp >> 1;      // 0..3
    int wn = warp & 1;       // 0..1

    float c[2][8][4];
#pragma unroll
    for (int mt = 0; mt < 2; mt++)
#pragma unroll
        for (int nt = 0; nt < 8; nt++)
#pragma unroll
            for (int i = 0; i < 4; i++) c[mt][nt][i] = 0.f;

    const float4* x4 = (const float4*)x;
    const float4* W4 = (const float4*)W;

#pragma unroll
    for (int kc = 0; kc < HID / GK; kc++) {
        int k0 = kc * GK;
        if (kc) __syncthreads();
#pragma unroll
        for (int i = 0; i < 4; i++) {
            int idx = tid + i * 256;
            int r = idx >> 3;          // 8 float4 per row
            int c4 = idx & 7;
            int gn = node0 + r;
            float4 val = (gn < NN) ? x4[(size_t)gn * 32 + (k0 >> 2) + c4]
                                   : make_float4(0.f, 0.f, 0.f, 0.f);
            *(uint4*)&As[r * PAD + c4 * 4] = f4_to_tf32(val);
        }
#pragma unroll
        for (int i = 0; i < 4; i++) {
            int idx = tid + i * 256;
            int r = idx >> 3;
            int c4 = idx & 7;
            *(uint4*)&Ws[r * PAD + c4 * 4] =
                f4_to_tf32(W4[(size_t)r * 32 + (k0 >> 2) + c4]);
        }
        __syncthreads();

#pragma unroll
        for (int ks = 0; ks < GK / 8; ks++) {
            int kk = ks * 8;
            uint32_t a[2][4];
#pragma unroll
            for (int mt = 0; mt < 2; mt++) {
                int mrow = wm * 32 + mt * 16;
                a[mt][0] = As[(mrow + g) * PAD + kk + t];
                a[mt][1] = As[(mrow + g + 8) * PAD + kk + t];
                a[mt][2] = As[(mrow + g) * PAD + kk + t + 4];
                a[mt][3] = As[(mrow + g + 8) * PAD + kk + t + 4];
            }
#pragma unroll
            for (int nt = 0; nt < 8; nt++) {
                int o = wn * 64 + nt * 8 + g;
                uint32_t b0 = Ws[o * PAD + kk + t];
                uint32_t b1 = Ws[o * PAD + kk + t + 4];
                mma_tf32(c[0][nt], a[0], b0, b1);
                mma_tf32(c[1][nt], a[1], b0, b1);
            }
        }
    }

    // Store. c[..][0..1] -> row (base+g) cols (2t, 2t+1); c[..][2..3] -> row+8.
    if (m == 0) {
#pragma unroll
        for (int mt = 0; mt < 2; mt++) {
            int r0 = node0 + wm * 32 + mt * 16 + g;
            int r1 = r0 + 8;
#pragma unroll
            for (int nt = 0; nt < 8; nt++) {
                int col = wn * 64 + nt * 8 + 2 * t;
                if (r0 < NN)
                    *(float2*)&g_q[(size_t)r0 * HID + col] =
                        make_float2(c[mt][nt][0], c[mt][nt][1]);
                if (r1 < NN)
                    *(float2*)&g_q[(size_t)r1 * HID + col] =
                        make_float2(c[mt][nt][2], c[mt][nt][3]);
            }
        }
    } else {
        __half2* outh = (m == 1) ? (__half2*)g_kh : (__half2*)g_vh;
#pragma unroll
        for (int mt = 0; mt < 2; mt++) {
            int r0 = node0 + wm * 32 + mt * 16 + g;
            int r1 = r0 + 8;
#pragma unroll
            for (int nt = 0; nt < 8; nt++) {
                int cp = wn * 32 + nt * 4 + t;   // col-pair index (col/2)
                if (r0 < NN)
                    outh[(size_t)r0 * (HID / 2) + cp] =
                        __floats2half2_rn(c[mt][nt][0], c[mt][nt][1]);
                if (r1 < NN)
                    outh[(size_t)r1 * (HID / 2) + cp] =
                        __floats2half2_rn(c[mt][nt][2], c[mt][nt][3]);
            }
        }
    }
}

// ---------------------------------------------------------------------------
// Kernel 2: FUSED dst-sorted edge kernel (warp = CTA = node, unroll 4).
// k,v now fp16 -> gather traffic halved (8B per lane per row). q fp32.
// ---------------------------------------------------------------------------
__global__ __launch_bounds__(32) void edge_fused(
    const float* __restrict__ w_ij,
    const float* __restrict__ cutoff,
    float* __restrict__ out) {

    int node = blockIdx.x;
    int l = threadIdx.x;

    int p     = g_start[node];
    int e_end = g_start[node + 1];

    float4 q = *(const float4*)&g_q[(size_t)node * HID + 4 * l];
    float4 acc = make_float4(0.f, 0.f, 0.f, 0.f);

    for (; p + 4 <= e_end; p += 4) {
        int2 es0 = g_es[p];
        int2 es1 = g_es[p + 1];
        int2 es2 = g_es[p + 2];
        int2 es3 = g_es[p + 3];

        float4 k0 = ld_half4(&g_kh[(size_t)es0.y * HID + 4 * l]);
        float4 k1 = ld_half4(&g_kh[(size_t)es1.y * HID + 4 * l]);
        float4 k2 = ld_half4(&g_kh[(size_t)es2.y * HID + 4 * l]);
        float4 k3 = ld_half4(&g_kh[(size_t)es3.y * HID + 4 * l]);
        float4 v0 = ld_half4(&g_vh[(size_t)es0.y * HID + 4 * l]);
        float4 v1 = ld_half4(&g_vh[(size_t)es1.y * HID + 4 * l]);
        float4 v2 = ld_half4(&g_vh[(size_t)es2.y * HID + 4 * l]);
        float4 v3 = ld_half4(&g_vh[(size_t)es3.y * HID + 4 * l]);
        float4 w0 = __ldcs((const float4*)&w_ij[(size_t)es0.x * HID + 4 * l]);
        float4 w1 = __ldcs((const float4*)&w_ij[(size_t)es1.x * HID + 4 * l]);
        float4 w2 = __ldcs((const float4*)&w_ij[(size_t)es2.x * HID + 4 * l]);
        float4 w3 = __ldcs((const float4*)&w_ij[(size_t)es3.x * HID + 4 * l]);
        float  c0 = __ldg(&cutoff[es0.x]);
        float  c1 = __ldg(&cutoff[es1.x]);
        float  c2 = __ldg(&cutoff[es2.x]);
        float  c3 = __ldg(&cutoff[es3.x]);

        float p0 = q.x * w0.x * k0.x + q.y * w0.y * k0.y + q.z * w0.z * k0.z + q.w * w0.w * k0.w;
        float p1 = q.x * w1.x * k1.x + q.y * w1.y * k1.y + q.z * w1.z * k1.z + q.w * w1.w * k1.w;
        float p2 = q.x * w2.x * k2.x + q.y * w2.y * k2.y + q.z * w2.z * k2.z + q.w * w2.w * k2.w;
        float p3 = q.x * w3.x * k3.x + q.y * w3.y * k3.y + q.z * w3.z * k3.z + q.w * w3.w * k3.w;

        p0 += __shfl_xor_sync(0xffffffffu, p0, 1);
        p0 += __shfl_xor_sync(0xffffffffu, p0, 2);
        p1 += __shfl_xor_sync(0xffffffffu, p1, 1);
        p1 += __shfl_xor_sync(0xffffffffu, p1, 2);
        p2 += __shfl_xor_sync(0xffffffffu, p2, 1);
        p2 += __shfl_xor_sync(0xffffffffu, p2, 2);
        p3 += __shfl_xor_sync(0xffffffffu, p3, 1);
        p3 += __shfl_xor_sync(0xffffffffu, p3, 2);

        float a0 = p0 * 0.25f * c0;
        float a1 = p1 * 0.25f * c1;
        float a2 = p2 * 0.25f * c2;
        float a3 = p3 * 0.25f * c3;

        acc.x = fmaf(a0, v0.x, fmaf(a1, v1.x, fmaf(a2, v2.x, fmaf(a3, v3.x, acc.x))));
        acc.y = fmaf(a0, v0.y, fmaf(a1, v1.y, fmaf(a2, v2.y, fmaf(a3, v3.y, acc.y))));
        acc.z = fmaf(a0, v0.z, fmaf(a1, v1.z, fmaf(a2, v2.z, fmaf(a3, v3.z, acc.z))));
        acc.w = fmaf(a0, v0.w, fmaf(a1, v1.w, fmaf(a2, v2.w, fmaf(a3, v3.w, acc.w))));
    }
    for (; p < e_end; p++) {
        int2 es0 = g_es[p];
        float4 k0 = ld_half4(&g_kh[(size_t)es0.y * HID + 4 * l]);
        float4 v0 = ld_half4(&g_vh[(size_t)es0.y * HID + 4 * l]);
        float4 w0 = __ldcs((const float4*)&w_ij[(size_t)es0.x * HID + 4 * l]);
        float p0 = q.x * w0.x * k0.x + q.y * w0.y * k0.y + q.z * w0.z * k0.z + q.w * w0.w * k0.w;
        p0 += __shfl_xor_sync(0xffffffffu, p0, 1);
        p0 += __shfl_xor_sync(0xffffffffu, p0, 2);
        float a0 = p0 * 0.25f * __ldg(&cutoff[es0.x]);
        acc.x = fmaf(a0, v0.x, acc.x);
        acc.y = fmaf(a0, v0.y, acc.y);
        acc.z = fmaf(a0, v0.z, acc.z);
        acc.w = fmaf(a0, v0.w, acc.w);
    }

    __stcs((float4*)&out[(size_t)node * HID + 4 * l], acc);
}

// ---------------------------------------------------------------------------
extern "C" void kernel_launch(void* const* d_in, const int* in_sizes, int n_in,
                              void* d_out, int out_size) {
    const float* x      = (const float*)d_in[0];
    const float* w_ij   = (const float*)d_in[1];
    const unsigned int* ei = (const unsigned int*)d_in[2];
    const float* cutoff = (const float*)d_in[3];
    const float* Wq     = (const float*)d_in[4];
    const float* Wk     = (const float*)d_in[5];
    const float* Wv     = (const float*)d_in[6];
    float* out = (float*)d_out;

    static cudaStream_t s2 = nullptr;
    static cudaEvent_t evFork = nullptr, evSort = nullptr;
    static bool use_streams = false;
    if (!s2 && !evFork) {
        bool ok = (cudaStreamCreateWithFlags(&s2, cudaStreamNonBlocking) == cudaSuccess)
               && (cudaEventCreateWithFlags(&evFork, cudaEventDisableTiming) == cudaSuccess)
               && (cudaEventCreateWithFlags(&evSort, cudaEventDisableTiming) == cudaSuccess);
        use_streams = ok;
    }

    dim3 ggrid((NN + GM - 1) / GM, 3);   // 391 x 3

    if (use_streams) {
        cudaEventRecord(evFork, 0);
        cudaStreamWaitEvent(s2, evFork, 0);

        // s2: sort chain (hidden under the GEMM on main)
        zero_and_detect<<<148, 256, 0, s2>>>(ei);
        convert_idx<<<148, 256, 0, s2>>>(ei);
        scan_phase1<<<NBLK, SCAN_B, 0, s2>>>();
        scan_phase2<<<1, 64, 0, s2>>>();
        scan_phase3<<<NBLK, SCAN_B, 0, s2>>>();
        permute_idx<<<148, 256, 0, s2>>>();
        cudaEventRecord(evSort, s2);

        // main: tensor-core QKV GEMM
        qkv_gemm_tc<<<ggrid, 256>>>(x, Wq, Wk, Wv);

        // join: fused edge needs sort + qkv
        cudaStreamWaitEvent(0, evSort, 0);
        edge_fused<<<NN, 32>>>(w_ij, cutoff, out);
    } else {
        zero_and_detect<<<148, 256>>>(ei);
        convert_idx<<<148, 256>>>(ei);
        scan_phase1<<<NBLK, SCAN_B>>>();
        scan_phase2<<<1, 64>>>();
        scan_phase3<<<NBLK, SCAN_B>>>();
        permute_idx<<<148, 256>>>();
        qkv_gemm_tc<<<ggrid, 256>>>(x, Wq, Wk, Wv);
        edge_fused<<<NN, 32>>>(w_ij, cutoff, out);
    }
}